// round 10
// baseline (speedup 1.0000x reference)
#include <cuda_runtime.h>
#include <cstdint>

// ---------------------------------------------------------------------------
// pitch_predictor: 4x BiLSTM(H=16) over T=2048, B=128 -> downsample 7::8 ->
// 4x LSTM(H=1) over 256 steps.
// R9: scan restructured — lane j owns unit j fully (gates i,f,g,o), no
//     shfl/select on the critical path; half-warp 0 = fwd, half-warp 1 = bwd
//     (one warp per batch). xW permuted to float4 (i,f,g,o) per unit.
//     Precompute layout updated to match; otherwise the verified R6 version.
// ---------------------------------------------------------------------------

#define Bn 128
#define Tn 2048
#define TU 256

typedef unsigned long long ull;

// Scratch (device globals; no allocation allowed)
__device__ float g_xWp[2ull * Bn * Tn * 64];   // unit-major, prescaled xW: [dir][b][t][j*4 + {i,f,g,o}]
__device__ float g_x[(size_t)Bn * Tn * 32];    // layer activations [b][t][32] (fwd 0..15, bwd 16..31)
__device__ float g_xu0[(size_t)Bn * TU * 4];   // upper layer-0 input projections (prescaled per gate)

// ---- HW tanh; sigmoid(x)=0.5*tanh(0.5x)+0.5 with 0.5 folded upstream ----
__device__ __forceinline__ float tanhf_a(float x) {
    float r; asm("tanh.approx.f32 %0, %1;" : "=f"(r) : "f"(x)); return r;
}

// ---- packed f32x2 helpers ----
__device__ __forceinline__ ull pk2(float lo, float hi) {
    ull r; asm("mov.b64 %0, {%1, %2};" : "=l"(r) : "f"(lo), "f"(hi)); return r;
}
__device__ __forceinline__ void upk2(float& lo, float& hi, ull v) {
    asm("mov.b64 {%0, %1}, %2;" : "=f"(lo), "=f"(hi) : "l"(v));
}
__device__ __forceinline__ ull fma2(ull a, ull b, ull c) {
    ull d; asm("fma.rn.f32x2 %0, %1, %2, %3;" : "=l"(d) : "l"(a), "l"(b), "l"(c)); return d;
}
__device__ __forceinline__ ull add2(ull a, ull b) {
    ull d; asm("add.rn.f32x2 %0, %1, %2;" : "=l"(d) : "l"(a), "l"(b)); return d;
}
__device__ __forceinline__ float hsum2(ull a, ull b) {
    float lo, hi; upk2(lo, hi, add2(a, b)); return lo + hi;
}

// ---------------------------------------------------------------------------
// Precompute xW for one bidir layer. Unit-major gate layout:
//   p = 4*j + gate, gate in {0:i,1:f,2:g,3:o}; original row r = gate*16 + j.
//   sigmoid gates (i,f,o) prescaled by 0.5; tanh gate (g) by 1.
// W staged coalesced into padded shared; LDS.128 x + FFMA2 dots (R6 scheme).
// ---------------------------------------------------------------------------
template <int CIN>
__global__ void __launch_bounds__(256) precompute_bidir(
    const float* __restrict__ xin, int use_gx,
    const float* __restrict__ Wih,   // [2][64][CIN]
    const float* __restrict__ bias)  // [2][64]
{
    constexpr int ROWS = 64;
    constexpr int PITCH = CIN + 2;
    __shared__ __align__(16) float xs[ROWS * CIN];
    __shared__ float Wt[128 * PITCH];

    for (int idx = threadIdx.x; idx < 128 * CIN; idx += 256) {
        const int r = idx / CIN;
        const int i = idx - r * CIN;
        Wt[r * PITCH + i] = Wih[idx];
    }
    const float* x = use_gx ? (const float*)g_x : xin;
    const int r0 = blockIdx.x * ROWS;
    {
        const float4* src = (const float4*)(x + (size_t)r0 * CIN);
        float4* dst = (float4*)xs;
        for (int i = threadIdx.x; i < ROWS * CIN / 4; i += 256) dst[i] = src[i];
    }
    __syncthreads();

    const int g = threadIdx.x & 127;       // dir*64 + p
    const int rh = threadIdx.x >> 7;       // row half (32 rows each)
    const int dir = g >> 6, p = g & 63;
    const int gate = p & 3;                // 0:i 1:f 2:g 3:o
    const int rw = gate * 16 + (p >> 2);   // original weight row
    const int r = dir * 64 + rw;
    const float sc = (gate == 2) ? 1.0f : 0.5f;

    ull w2[CIN / 2];
#pragma unroll
    for (int k = 0; k < CIN / 2; k++)
        w2[k] = pk2(Wt[r * PITCH + 2 * k] * sc, Wt[r * PITCH + 2 * k + 1] * sc);
    const float bv = bias[r] * sc;

    float* outd = g_xWp + (size_t)dir * Bn * Tn * 64;
#pragma unroll
    for (int rb = 0; rb < 32; rb += 4) {
        const int row0 = rh * 32 + rb;
        ull acc0 = pk2(bv, 0.f), acc1 = pk2(bv, 0.f), acc2 = pk2(bv, 0.f), acc3 = pk2(bv, 0.f);
#pragma unroll
        for (int ii = 0; ii < CIN; ii += 4) {
            const ulonglong2 x0 = *(const ulonglong2*)&xs[(row0 + 0) * CIN + ii];
            const ulonglong2 x1 = *(const ulonglong2*)&xs[(row0 + 1) * CIN + ii];
            const ulonglong2 x2 = *(const ulonglong2*)&xs[(row0 + 2) * CIN + ii];
            const ulonglong2 x3 = *(const ulonglong2*)&xs[(row0 + 3) * CIN + ii];
            const ull wa = w2[ii / 2], wb2 = w2[ii / 2 + 1];
            acc0 = fma2(wa, x0.x, acc0); acc0 = fma2(wb2, x0.y, acc0);
            acc1 = fma2(wa, x1.x, acc1); acc1 = fma2(wb2, x1.y, acc1);
            acc2 = fma2(wa, x2.x, acc2); acc2 = fma2(wb2, x2.y, acc2);
            acc3 = fma2(wa, x3.x, acc3); acc3 = fma2(wb2, x3.y, acc3);
        }
        float lo, hi2;
        upk2(lo, hi2, acc0); outd[(size_t)(r0 + row0 + 0) * 64 + p] = lo + hi2;
        upk2(lo, hi2, acc1); outd[(size_t)(r0 + row0 + 1) * 64 + p] = lo + hi2;
        upk2(lo, hi2, acc2); outd[(size_t)(r0 + row0 + 2) * 64 + p] = lo + hi2;
        upk2(lo, hi2, acc3); outd[(size_t)(r0 + row0 + 3) * 64 + p] = lo + hi2;
    }
}

// ---------------------------------------------------------------------------
// Bidirectional scan: ONE warp per batch. Lanes 0-15 = forward chain,
// lanes 16-31 = backward chain. Lane j of each half owns unit j: computes
// gates i,f,g,o via 4x16 fma2 dots, updates (c_j,h_j), stores h_j to its
// direction's double-buffered shared h (no sync: converged-warp in-order
// STS -> LDS). No shuffles, no predication in the loop.
// ---------------------------------------------------------------------------
__global__ void __launch_bounds__(32) scan_bidir(const float* __restrict__ Whh /* [2][64][16] */)
{
    __shared__ __align__(16) float hbuf[2][2][16];   // [dir][parity][j]

    const int b = blockIdx.x;
    const int lane = threadIdx.x;
    const int dir = lane >> 4;
    const int j = lane & 15;

    // Recurrent weights for unit j: rows j (i), 16+j (f), 32+j (g), 48+j (o)
    const float* wb = Whh + dir * 64 * 16;
    ull WI[8], WF[8], WG[8], WO[8];
#pragma unroll
    for (int k = 0; k < 8; k++) {
        WI[k] = pk2(wb[j * 16 + 2 * k] * 0.5f,        wb[j * 16 + 2 * k + 1] * 0.5f);
        WF[k] = pk2(wb[(16 + j) * 16 + 2 * k] * 0.5f, wb[(16 + j) * 16 + 2 * k + 1] * 0.5f);
        WG[k] = pk2(wb[(32 + j) * 16 + 2 * k],        wb[(32 + j) * 16 + 2 * k + 1]);
        WO[k] = pk2(wb[(48 + j) * 16 + 2 * k] * 0.5f, wb[(48 + j) * 16 + 2 * k + 1] * 0.5f);
    }

    const uint32_t hb = (uint32_t)__cvta_generic_to_shared(hbuf) + (dir << 7);
    hbuf[dir][0][j] = 0.f;
    hbuf[dir][1][j] = 0.f;
    __syncwarp();   // once, outside the loop

    float c = 0.f;

    const int tstart = dir ? (Tn - 1) : 0;
    const int tstep = dir ? -1 : 1;
    // per-lane xW pointer (float4 = unit j's 4 gates), stride 16 float4 per t
    const float4* pbase = (const float4*)(g_xWp + ((size_t)dir * Bn + b) * Tn * 64) + j;

    const int PF = 4;
    float4 buf[PF];
#pragma unroll
    for (int s = 0; s < PF; s++)
        buf[s] = pbase[(long)(tstart + s * tstep) * 16];

    // output pointer: g_x[b][t][dir*16 + j]
    float* outb = g_x + (size_t)b * Tn * 32 + dir * 16 + j;

    for (int it = 0; it < Tn; it += PF) {
#pragma unroll
        for (int s = 0; s < PF; s++) {
            const int st = it + s;
            const float4 xw = buf[s];
            // unguarded tail prefetch: stays inside g_xWp (see chain layout)
            buf[s] = pbase[(long)(tstart + (st + PF) * tstep) * 16];

            // packed h pairs for this direction (4x LDS.128, half-warp broadcast)
            const uint32_t rdb = hb + ((st & 1) << 6);
            ull q0, q1, q2, q3, q4, q5, q6, q7;
            asm volatile("ld.shared.v2.b64 {%0,%1},[%2];" : "=l"(q0), "=l"(q1) : "r"(rdb));
            asm volatile("ld.shared.v2.b64 {%0,%1},[%2];" : "=l"(q2), "=l"(q3) : "r"(rdb + 16));
            asm volatile("ld.shared.v2.b64 {%0,%1},[%2];" : "=l"(q4), "=l"(q5) : "r"(rdb + 32));
            asm volatile("ld.shared.v2.b64 {%0,%1},[%2];" : "=l"(q6), "=l"(q7) : "r"(rdb + 48));

            // four 16-dots, split accumulators (4-deep chains)
            ull aI0 = pk2(xw.x, 0.f), aI1 = 0ull;
            ull aF0 = pk2(xw.y, 0.f), aF1 = 0ull;
            ull aG0 = pk2(xw.z, 0.f), aG1 = 0ull;
            ull aO0 = pk2(xw.w, 0.f), aO1 = 0ull;
            aF0 = fma2(WF[0], q0, aF0); aI0 = fma2(WI[0], q0, aI0);
            aG0 = fma2(WG[0], q0, aG0); aO0 = fma2(WO[0], q0, aO0);
            aF0 = fma2(WF[1], q1, aF0); aI0 = fma2(WI[1], q1, aI0);
            aG0 = fma2(WG[1], q1, aG0); aO0 = fma2(WO[1], q1, aO0);
            aF0 = fma2(WF[2], q2, aF0); aI0 = fma2(WI[2], q2, aI0);
            aG0 = fma2(WG[2], q2, aG0); aO0 = fma2(WO[2], q2, aO0);
            aF0 = fma2(WF[3], q3, aF0); aI0 = fma2(WI[3], q3, aI0);
            aG0 = fma2(WG[3], q3, aG0); aO0 = fma2(WO[3], q3, aO0);
            aF1 = fma2(WF[4], q4, aF1); aI1 = fma2(WI[4], q4, aI1);
            aG1 = fma2(WG[4], q4, aG1); aO1 = fma2(WO[4], q4, aO1);
            aF1 = fma2(WF[5], q5, aF1); aI1 = fma2(WI[5], q5, aI1);
            aG1 = fma2(WG[5], q5, aG1); aO1 = fma2(WO[5], q5, aO1);
            aF1 = fma2(WF[6], q6, aF1); aI1 = fma2(WI[6], q6, aI1);
            aG1 = fma2(WG[6], q6, aG1); aO1 = fma2(WO[6], q6, aO1);
            aF1 = fma2(WF[7], q7, aF1); aI1 = fma2(WI[7], q7, aI1);
            aG1 = fma2(WG[7], q7, aG1); aO1 = fma2(WO[7], q7, aO1);

            const float preF = hsum2(aF0, aF1);
            const float preI = hsum2(aI0, aI1);
            const float preG = hsum2(aG0, aG1);
            const float preO = hsum2(aO0, aO1);

            const float sF = fmaf(0.5f, tanhf_a(preF), 0.5f);
            const float sI = fmaf(0.5f, tanhf_a(preI), 0.5f);
            const float tG = tanhf_a(preG);
            const float sO = fmaf(0.5f, tanhf_a(preO), 0.5f);

            c = fmaf(sF, c, sI * tG);
            const float hn = sO * tanhf_a(c);

            // store into the other parity buffer; next LDS sees it in-order
            const uint32_t wrb = hb + (((st & 1) ^ 1) << 6) + (j << 2);
            asm volatile("st.shared.b32 [%0], %1;" :: "r"(wrb), "f"(hn));

            const int t = tstart + st * tstep;
            outb[(size_t)t * 32] = hn;
        }
    }
}

// ---------------------------------------------------------------------------
// Upper layer-0 input projection with fused downsample (gate-prescaled).
// ---------------------------------------------------------------------------
__global__ void __launch_bounds__(256) precompute_upper(
    const float* __restrict__ uWih0, const float* __restrict__ ub)
{
    __shared__ float W[4][32];
    __shared__ float bb4[4];
    if (threadIdx.x < 128) {
        const int gg = threadIdx.x >> 5;
        const float s = (gg == 2) ? 1.0f : 0.5f;
        W[gg][threadIdx.x & 31] = uWih0[threadIdx.x] * s;
    }
    if (threadIdx.x < 4) {
        const float s = (threadIdx.x == 2) ? 1.0f : 0.5f;
        bb4[threadIdx.x] = ub[threadIdx.x] * s;
    }
    __syncthreads();

    const int b = blockIdx.x, u = threadIdx.x;
    const float* xr = g_x + ((size_t)b * Tn + 7 + 8 * u) * 32;
    float a0 = bb4[0], a1 = bb4[1], a2 = bb4[2], a3 = bb4[3];
#pragma unroll
    for (int i = 0; i < 32; i++) {
        const float xv = xr[i];
        a0 = fmaf(W[0][i], xv, a0);
        a1 = fmaf(W[1][i], xv, a1);
        a2 = fmaf(W[2][i], xv, a2);
        a3 = fmaf(W[3][i], xv, a3);
    }
    *(float4*)(g_xu0 + ((size_t)b * TU + u) * 4) = make_float4(a0, a1, a2, a3);
}

// ---------------------------------------------------------------------------
// Upper stack: 4 fused unidirectional LSTM layers with H=1, one thread/batch.
// ---------------------------------------------------------------------------
__global__ void __launch_bounds__(32) scan_upper(
    const float* __restrict__ uWih,  // [3][4]
    const float* __restrict__ uWhh,  // [4][4]
    const float* __restrict__ ub,    // [4][4]
    float* __restrict__ out)         // [B][256]
{
    const int b = blockIdx.x * 32 + threadIdx.x;
    float wih[3][4], whh[4][4], bu[4][4];
#pragma unroll
    for (int l = 0; l < 3; l++)
#pragma unroll
        for (int g = 0; g < 4; g++) {
            const float s = (g == 2) ? 1.0f : 0.5f;
            wih[l][g] = uWih[l * 4 + g] * s;
        }
#pragma unroll
    for (int l = 0; l < 4; l++)
#pragma unroll
        for (int g = 0; g < 4; g++) {
            const float s = (g == 2) ? 1.0f : 0.5f;
            whh[l][g] = uWhh[l * 4 + g] * s;
            bu[l][g] = ub[l * 4 + g] * s;
        }

    float h[4] = {0.f, 0.f, 0.f, 0.f}, c[4] = {0.f, 0.f, 0.f, 0.f};
    const float4* xp = (const float4*)g_xu0 + (size_t)b * TU;

    for (int u = 0; u < TU; u++) {
        const float4 p = xp[u];
        {
            const float pi = fmaf(whh[0][0], h[0], p.x);
            const float pf = fmaf(whh[0][1], h[0], p.y);
            const float pg = fmaf(whh[0][2], h[0], p.z);
            const float po = fmaf(whh[0][3], h[0], p.w);
            const float ii = fmaf(0.5f, tanhf_a(pi), 0.5f);
            const float ff = fmaf(0.5f, tanhf_a(pf), 0.5f);
            const float gg = tanhf_a(pg);
            const float oo = fmaf(0.5f, tanhf_a(po), 0.5f);
            c[0] = fmaf(ff, c[0], ii * gg);
            h[0] = oo * tanhf_a(c[0]);
        }
#pragma unroll
        for (int l = 1; l < 4; l++) {
            const float pi = fmaf(wih[l - 1][0], h[l - 1], fmaf(whh[l][0], h[l], bu[l][0]));
            const float pf = fmaf(wih[l - 1][1], h[l - 1], fmaf(whh[l][1], h[l], bu[l][1]));
            const float pg = fmaf(wih[l - 1][2], h[l - 1], fmaf(whh[l][2], h[l], bu[l][2]));
            const float po = fmaf(wih[l - 1][3], h[l - 1], fmaf(whh[l][3], h[l], bu[l][3]));
            const float ii = fmaf(0.5f, tanhf_a(pi), 0.5f);
            const float ff = fmaf(0.5f, tanhf_a(pf), 0.5f);
            const float gg = tanhf_a(pg);
            const float oo = fmaf(0.5f, tanhf_a(po), 0.5f);
            c[l] = fmaf(ff, c[l], ii * gg);
            h[l] = oo * tanhf_a(c[l]);
        }
        out[(size_t)b * TU + u] = h[3];
    }
}

// ---------------------------------------------------------------------------
extern "C" void kernel_launch(void* const* d_in, const int* in_sizes, int n_in,
                              void* d_out, int out_size)
{
    (void)in_sizes; (void)n_in; (void)out_size;
    const float* x0    = (const float*)d_in[0];  // [128,2048,24]
    const float* bWih0 = (const float*)d_in[1];  // [2,64,24]
    const float* bWih  = (const float*)d_in[2];  // [3,2,64,32]
    const float* bWhh  = (const float*)d_in[3];  // [4,2,64,16]
    const float* bb    = (const float*)d_in[4];  // [4,2,64]
    const float* uWih0 = (const float*)d_in[5];  // [4,32]
    const float* uWih  = (const float*)d_in[6];  // [3,4,1]
    const float* uWhh  = (const float*)d_in[7];  // [4,4,1]
    const float* ub    = (const float*)d_in[8];  // [4,4]

    const int nblk = (Bn * Tn) / 64;  // 4096

    for (int l = 0; l < 4; l++) {
        if (l == 0)
            precompute_bidir<24><<<nblk, 256>>>(x0, 0, bWih0, bb);
        else
            precompute_bidir<32><<<nblk, 256>>>(nullptr, 1,
                                                bWih + (size_t)(l - 1) * 2 * 64 * 32,
                                                bb + (size_t)l * 128);
        scan_bidir<<<Bn, 32>>>(bWhh + (size_t)l * 2 * 64 * 16);
    }
    precompute_upper<<<Bn, 256>>>(uWih0, ub);
    scan_upper<<<Bn / 32, 32>>>(uWih, uWhh, ub, (float*)d_out);
}

// round 11
// speedup vs baseline: 1.3496x; 1.3496x over previous
#include <cuda_runtime.h>
#include <cstdint>

// ---------------------------------------------------------------------------
// pitch_predictor: 4x BiLSTM(H=16) over T=2048, B=128 -> downsample 7::8 ->
// 4x LSTM(H=1) over 256 steps.
// R10: scan reverted to the verified R8 version (two lanes per unit, shared
//      h broadcast, no per-step sync). Precompute made persistent: 512 blocks
//      x 8 tiles, W staged once per block, x double-buffered through regs.
// ---------------------------------------------------------------------------

#define Bn 128
#define Tn 2048
#define TU 256

typedef unsigned long long ull;

// Scratch (device globals; no allocation allowed)
__device__ float g_xWp[2ull * Bn * Tn * 64];   // gate-permuted, prescaled xW [dir][b][t][64], p=2*(r&31)+(r>>5)
__device__ float g_x[(size_t)Bn * Tn * 32];    // layer activations [b][t][32] (fwd 0..15, bwd 16..31)
__device__ float g_xu0[(size_t)Bn * TU * 4];   // upper layer-0 input projections (prescaled per gate)

// ---- HW tanh; sigmoid(x)=0.5*tanh(0.5x)+0.5 with 0.5 folded upstream ----
__device__ __forceinline__ float tanhf_a(float x) {
    float r; asm("tanh.approx.f32 %0, %1;" : "=f"(r) : "f"(x)); return r;
}

// ---- packed f32x2 helpers ----
__device__ __forceinline__ ull pk2(float lo, float hi) {
    ull r; asm("mov.b64 %0, {%1, %2};" : "=l"(r) : "f"(lo), "f"(hi)); return r;
}
__device__ __forceinline__ void upk2(float& lo, float& hi, ull v) {
    asm("mov.b64 {%0, %1}, %2;" : "=f"(lo), "=f"(hi) : "l"(v));
}
__device__ __forceinline__ ull fma2(ull a, ull b, ull c) {
    ull d; asm("fma.rn.f32x2 %0, %1, %2, %3;" : "=l"(d) : "l"(a), "l"(b), "l"(c)); return d;
}
__device__ __forceinline__ ull add2(ull a, ull b) {
    ull d; asm("add.rn.f32x2 %0, %1, %2;" : "=l"(d) : "l"(a), "l"(b)); return d;
}

// gate rows within 64: [0,16)=i [16,32)=f [32,48)=g [48,64)=o
__device__ __forceinline__ float gate_scale64(int row) {
    return (row < 32 || row >= 48) ? 0.5f : 1.0f;
}

// ---------------------------------------------------------------------------
// Persistent precompute: each block owns NT=8 consecutive 64-row tiles.
// W staged to shared once, picked into registers once; per tile, x is
// prefetched into registers during compute and committed to shared between
// two light syncs. Layout/math identical to the verified R8 precompute.
// ---------------------------------------------------------------------------
template <int CIN>
__global__ void __launch_bounds__(256) precompute_bidir(
    const float* __restrict__ xin, int use_gx,
    const float* __restrict__ Wih,   // [2][64][CIN]
    const float* __restrict__ bias)  // [2][64]
{
    constexpr int ROWS = 64;
    constexpr int NT = 8;
    constexpr int PITCH = CIN + 2;
    constexpr int XF4 = ROWS * CIN / 4;          // float4s per tile (384 or 512)
    constexpr int NPF = (XF4 + 255) / 256;       // per-thread prefetch regs (<=2)

    __shared__ __align__(16) float xs[ROWS * CIN];
    __shared__ float Wt[128 * PITCH];

    // Stage W once (coalesced LDG, conflict-free STS)
    for (int idx = threadIdx.x; idx < 128 * CIN; idx += 256) {
        const int r = idx / CIN;
        const int i = idx - r * CIN;
        Wt[r * PITCH + i] = Wih[idx];
    }
    const float* x = use_gx ? (const float*)g_x : xin;
    const int tile0 = blockIdx.x * NT;

    // Stage x tile 0
    {
        const float4* src = (const float4*)(x + (size_t)tile0 * ROWS * CIN);
        float4* dst = (float4*)xs;
#pragma unroll
        for (int k = 0; k < NPF; k++) {
            const int i = threadIdx.x + k * 256;
            if (i < XF4) dst[i] = src[i];
        }
    }
    __syncthreads();

    const int g = threadIdx.x & 127;       // dir*64 + p
    const int rh = threadIdx.x >> 7;       // row half (32 rows each)
    const int dir = g >> 6, p = g & 63;
    const int rw = ((p & 1) << 5) + (p >> 1);
    const int r = dir * 64 + rw;
    const float sc = gate_scale64(rw);

    // Pick weights into registers once (held across all NT tiles)
    ull w2[CIN / 2];
#pragma unroll
    for (int k = 0; k < CIN / 2; k++)
        w2[k] = pk2(Wt[r * PITCH + 2 * k] * sc, Wt[r * PITCH + 2 * k + 1] * sc);
    const float bv = bias[r] * sc;

    float* outd = g_xWp + (size_t)dir * Bn * Tn * 64;

    for (int tt = 0; tt < NT; tt++) {
        const int r0 = (tile0 + tt) * ROWS;

        // Prefetch next tile's x into registers (overlaps with compute)
        float4 pf[NPF];
        if (tt + 1 < NT) {
            const float4* srcn = (const float4*)(x + (size_t)(r0 + ROWS) * CIN);
#pragma unroll
            for (int k = 0; k < NPF; k++) {
                const int i = threadIdx.x + k * 256;
                if (i < XF4) pf[k] = srcn[i];
            }
        }

        // Compute this tile
#pragma unroll
        for (int rb = 0; rb < 32; rb += 4) {
            const int row0 = rh * 32 + rb;
            ull acc0 = pk2(bv, 0.f), acc1 = pk2(bv, 0.f), acc2 = pk2(bv, 0.f), acc3 = pk2(bv, 0.f);
#pragma unroll
            for (int ii = 0; ii < CIN; ii += 4) {
                const ulonglong2 x0 = *(const ulonglong2*)&xs[(row0 + 0) * CIN + ii];
                const ulonglong2 x1 = *(const ulonglong2*)&xs[(row0 + 1) * CIN + ii];
                const ulonglong2 x2 = *(const ulonglong2*)&xs[(row0 + 2) * CIN + ii];
                const ulonglong2 x3 = *(const ulonglong2*)&xs[(row0 + 3) * CIN + ii];
                const ull wa = w2[ii / 2], wb2 = w2[ii / 2 + 1];
                acc0 = fma2(wa, x0.x, acc0); acc0 = fma2(wb2, x0.y, acc0);
                acc1 = fma2(wa, x1.x, acc1); acc1 = fma2(wb2, x1.y, acc1);
                acc2 = fma2(wa, x2.x, acc2); acc2 = fma2(wb2, x2.y, acc2);
                acc3 = fma2(wa, x3.x, acc3); acc3 = fma2(wb2, x3.y, acc3);
            }
            float lo, hi2;
            upk2(lo, hi2, acc0); outd[(size_t)(r0 + row0 + 0) * 64 + p] = lo + hi2;
            upk2(lo, hi2, acc1); outd[(size_t)(r0 + row0 + 1) * 64 + p] = lo + hi2;
            upk2(lo, hi2, acc2); outd[(size_t)(r0 + row0 + 2) * 64 + p] = lo + hi2;
            upk2(lo, hi2, acc3); outd[(size_t)(r0 + row0 + 3) * 64 + p] = lo + hi2;
        }

        // Commit prefetched tile to shared
        if (tt + 1 < NT) {
            __syncthreads();
            float4* dst = (float4*)xs;
#pragma unroll
            for (int k = 0; k < NPF; k++) {
                const int i = threadIdx.x + k * 256;
                if (i < XF4) dst[i] = pf[k];
            }
            __syncthreads();
        }
    }
}

// ---------------------------------------------------------------------------
// Bidirectional scan (exact R8 version — verified 320us): one warp per
// (b, dir). Lane j<16 owns (i_j, g_j), lane j+16 owns (f_j, o_j); both
// compute identical (c_j, h_j). h broadcast via warp-converged shared memory
// (no per-step sync); dots via fma.rn.f32x2 on pre-packed LDS pairs.
// ---------------------------------------------------------------------------
__global__ void __launch_bounds__(32) scan_bidir(const float* __restrict__ Whh /* [2][64][16] */)
{
    __shared__ __align__(16) float hbuf[2][16];

    const int b = blockIdx.x;
    const int dir = blockIdx.y;
    const int lane = threadIdx.x;
    const int hi = lane >> 4;

    const float* wb = Whh + dir * 64 * 16;
    const float sB_w = hi ? 0.5f : 1.0f;   // B gate: o (sig) vs g (tanh)
    ull WA2[8], WB2[8];
    {
        const float* wA = wb + lane * 16;
        const float* wB = wb + (32 + lane) * 16;
#pragma unroll
        for (int k = 0; k < 8; k++) {
            WA2[k] = pk2(wA[2 * k] * 0.5f, wA[2 * k + 1] * 0.5f);
            WB2[k] = pk2(wB[2 * k] * sB_w, wB[2 * k + 1] * sB_w);
        }
    }
    const float aB = hi ? 0.5f : 1.0f;
    const float cBc = hi ? 0.5f : 0.0f;

    const uint32_t hb = (uint32_t)__cvta_generic_to_shared(hbuf);
    if (!hi) { hbuf[0][lane] = 0.f; hbuf[1][lane] = 0.f; }
    __syncwarp();   // once, outside the loop

    float c = 0.f;
    const ull z64 = 0ull;

    const size_t chain = ((size_t)dir * Bn + b) * Tn;
    const float* pbase = g_xWp + chain * 64 + 2 * lane;
    const int tstart = dir ? (Tn - 1) : 0;
    const int tstep = dir ? -1 : 1;

    const int PF = 8;
    float2 buf[PF];
#pragma unroll
    for (int s = 0; s < PF; s++)
        buf[s] = *(const float2*)(pbase + (long)(tstart + s * tstep) * 64);

    float* outb = g_x + (size_t)b * Tn * 32 + dir * 16 + lane;  // lane<16 writes

    for (int it = 0; it < Tn; it += PF) {
#pragma unroll
        for (int s = 0; s < PF; s++) {
            const int st = it + s;
            const float2 xw = buf[s];
            // unguarded tail prefetch: stays inside g_xWp, values never consumed
            buf[s] = *(const float2*)(pbase + (long)(tstart + (st + PF) * tstep) * 64);

            // packed h pairs: 4x LDS.128 (all-lane broadcast), in order after
            // the previous iteration's STS within this converged warp.
            const uint32_t rdb = hb + ((st & 1) << 6);
            ull q0, q1, q2, q3, q4, q5, q6, q7;
            asm volatile("ld.shared.v2.b64 {%0,%1},[%2];" : "=l"(q0), "=l"(q1) : "r"(rdb));
            asm volatile("ld.shared.v2.b64 {%0,%1},[%2];" : "=l"(q2), "=l"(q3) : "r"(rdb + 16));
            asm volatile("ld.shared.v2.b64 {%0,%1},[%2];" : "=l"(q4), "=l"(q5) : "r"(rdb + 32));
            asm volatile("ld.shared.v2.b64 {%0,%1},[%2];" : "=l"(q6), "=l"(q7) : "r"(rdb + 48));

            ull accA0 = pk2(xw.x, 0.f), accA1 = z64;
            ull accB0 = pk2(xw.y, 0.f), accB1 = z64;
            accA0 = fma2(WA2[0], q0, accA0); accB0 = fma2(WB2[0], q0, accB0);
            accA0 = fma2(WA2[1], q1, accA0); accB0 = fma2(WB2[1], q1, accB0);
            accA0 = fma2(WA2[2], q2, accA0); accB0 = fma2(WB2[2], q2, accB0);
            accA0 = fma2(WA2[3], q3, accA0); accB0 = fma2(WB2[3], q3, accB0);
            accA1 = fma2(WA2[4], q4, accA1); accB1 = fma2(WB2[4], q4, accB1);
            accA1 = fma2(WA2[5], q5, accA1); accB1 = fma2(WB2[5], q5, accB1);
            accA1 = fma2(WA2[6], q6, accA1); accB1 = fma2(WB2[6], q6, accB1);
            accA1 = fma2(WA2[7], q7, accA1); accB1 = fma2(WB2[7], q7, accB1);

            float alo, ahi, blo, bhi;
            upk2(alo, ahi, add2(accA0, accA1));
            upk2(blo, bhi, add2(accB0, accB1));
            const float preA = alo + ahi;
            const float preB = blo + bhi;

            const float sA = fmaf(0.5f, tanhf_a(preA), 0.5f);   // sig(i) / sig(f)
            const float sB = fmaf(aB, tanhf_a(preB), cBc);      // tanh(g) / sig(o)

            const float oA = __shfl_xor_sync(0xffffffffu, sA, 16);
            const float oB = __shfl_xor_sync(0xffffffffu, sB, 16);

            const float f_ = hi ? sA : oA;
            const float i_ = hi ? oA : sA;
            const float g_ = hi ? oB : sB;
            const float o_ = hi ? sB : oB;

            c = fmaf(f_, c, i_ * g_);
            const float hn = o_ * tanhf_a(c);

            // predicated STS into the other buffer; next iteration's LDS sees
            // it via in-order same-warp shared access (warp stays converged).
            const uint32_t wrb = hb + (((st & 1) ^ 1) << 6) + (lane << 2);
            if (!hi)
                asm volatile("st.shared.b32 [%0], %1;" :: "r"(wrb), "f"(hn));

            const int t = tstart + st * tstep;
            if (!hi) outb[(size_t)t * 32] = hn;
        }
    }
}

// ---------------------------------------------------------------------------
// Upper layer-0 input projection with fused downsample (gate-prescaled).
// ---------------------------------------------------------------------------
__global__ void __launch_bounds__(256) precompute_upper(
    const float* __restrict__ uWih0, const float* __restrict__ ub)
{
    __shared__ float W[4][32];
    __shared__ float bb4[4];
    if (threadIdx.x < 128) {
        const int gg = threadIdx.x >> 5;
        const float s = (gg == 2) ? 1.0f : 0.5f;
        W[gg][threadIdx.x & 31] = uWih0[threadIdx.x] * s;
    }
    if (threadIdx.x < 4) {
        const float s = (threadIdx.x == 2) ? 1.0f : 0.5f;
        bb4[threadIdx.x] = ub[threadIdx.x] * s;
    }
    __syncthreads();

    const int b = blockIdx.x, u = threadIdx.x;
    const float* xr = g_x + ((size_t)b * Tn + 7 + 8 * u) * 32;
    float a0 = bb4[0], a1 = bb4[1], a2 = bb4[2], a3 = bb4[3];
#pragma unroll
    for (int i = 0; i < 32; i++) {
        const float xv = xr[i];
        a0 = fmaf(W[0][i], xv, a0);
        a1 = fmaf(W[1][i], xv, a1);
        a2 = fmaf(W[2][i], xv, a2);
        a3 = fmaf(W[3][i], xv, a3);
    }
    *(float4*)(g_xu0 + ((size_t)b * TU + u) * 4) = make_float4(a0, a1, a2, a3);
}

// ---------------------------------------------------------------------------
// Upper stack: 4 fused unidirectional LSTM layers with H=1, one thread/batch.
// ---------------------------------------------------------------------------
__global__ void __launch_bounds__(32) scan_upper(
    const float* __restrict__ uWih,  // [3][4]
    const float* __restrict__ uWhh,  // [4][4]
    const float* __restrict__ ub,    // [4][4]
    float* __restrict__ out)         // [B][256]
{
    const int b = blockIdx.x * 32 + threadIdx.x;
    float wih[3][4], whh[4][4], bu[4][4];
#pragma unroll
    for (int l = 0; l < 3; l++)
#pragma unroll
        for (int g = 0; g < 4; g++) {
            const float s = (g == 2) ? 1.0f : 0.5f;
            wih[l][g] = uWih[l * 4 + g] * s;
        }
#pragma unroll
    for (int l = 0; l < 4; l++)
#pragma unroll
        for (int g = 0; g < 4; g++) {
            const float s = (g == 2) ? 1.0f : 0.5f;
            whh[l][g] = uWhh[l * 4 + g] * s;
            bu[l][g] = ub[l * 4 + g] * s;
        }

    float h[4] = {0.f, 0.f, 0.f, 0.f}, c[4] = {0.f, 0.f, 0.f, 0.f};
    const float4* xp = (const float4*)g_xu0 + (size_t)b * TU;

    for (int u = 0; u < TU; u++) {
        const float4 p = xp[u];
        {
            const float pi = fmaf(whh[0][0], h[0], p.x);
            const float pf = fmaf(whh[0][1], h[0], p.y);
            const float pg = fmaf(whh[0][2], h[0], p.z);
            const float po = fmaf(whh[0][3], h[0], p.w);
            const float ii = fmaf(0.5f, tanhf_a(pi), 0.5f);
            const float ff = fmaf(0.5f, tanhf_a(pf), 0.5f);
            const float gg = tanhf_a(pg);
            const float oo = fmaf(0.5f, tanhf_a(po), 0.5f);
            c[0] = fmaf(ff, c[0], ii * gg);
            h[0] = oo * tanhf_a(c[0]);
        }
#pragma unroll
        for (int l = 1; l < 4; l++) {
            const float pi = fmaf(wih[l - 1][0], h[l - 1], fmaf(whh[l][0], h[l], bu[l][0]));
            const float pf = fmaf(wih[l - 1][1], h[l - 1], fmaf(whh[l][1], h[l], bu[l][1]));
            const float pg = fmaf(wih[l - 1][2], h[l - 1], fmaf(whh[l][2], h[l], bu[l][2]));
            const float po = fmaf(wih[l - 1][3], h[l - 1], fmaf(whh[l][3], h[l], bu[l][3]));
            const float ii = fmaf(0.5f, tanhf_a(pi), 0.5f);
            const float ff = fmaf(0.5f, tanhf_a(pf), 0.5f);
            const float gg = tanhf_a(pg);
            const float oo = fmaf(0.5f, tanhf_a(po), 0.5f);
            c[l] = fmaf(ff, c[l], ii * gg);
            h[l] = oo * tanhf_a(c[l]);
        }
        out[(size_t)b * TU + u] = h[3];
    }
}

// ---------------------------------------------------------------------------
extern "C" void kernel_launch(void* const* d_in, const int* in_sizes, int n_in,
                              void* d_out, int out_size)
{
    (void)in_sizes; (void)n_in; (void)out_size;
    const float* x0    = (const float*)d_in[0];  // [128,2048,24]
    const float* bWih0 = (const float*)d_in[1];  // [2,64,24]
    const float* bWih  = (const float*)d_in[2];  // [3,2,64,32]
    const float* bWhh  = (const float*)d_in[3];  // [4,2,64,16]
    const float* bb    = (const float*)d_in[4];  // [4,2,64]
    const float* uWih0 = (const float*)d_in[5];  // [4,32]
    const float* uWih  = (const float*)d_in[6];  // [3,4,1]
    const float* uWhh  = (const float*)d_in[7];  // [4,4,1]
    const float* ub    = (const float*)d_in[8];  // [4,4]

    const int nblk = (Bn * Tn) / (64 * 8);  // 512 persistent blocks (8 tiles each)

    for (int l = 0; l < 4; l++) {
        if (l == 0)
            precompute_bidir<24><<<nblk, 256>>>(x0, 0, bWih0, bb);
        else
            precompute_bidir<32><<<nblk, 256>>>(nullptr, 1,
                                                bWih + (size_t)(l - 1) * 2 * 64 * 32,
                                                bb + (size_t)l * 128);
        scan_bidir<<<dim3(Bn, 2), 32>>>(bWhh + (size_t)l * 2 * 64 * 16);
    }
    precompute_upper<<<Bn, 256>>>(uWih0, ub);
    scan_upper<<<Bn / 32, 32>>>(uWih, uWhh, ub, (float*)d_out);
}